// round 15
// baseline (speedup 1.0000x reference)
#include <cuda_runtime.h>
#include <cstdint>

#define SS   2048
#define HH   256
#define DXE  320
#define NT   64

// ---------------- device scratch (no allocations allowed) ----------------
__device__ float  g_x[SS * DXE];
__device__ float  g_gx[2 * SS * 1024];
__device__ float  g_hall[2 * SS * HH];
__device__ float  g_feats[SS * NT];
__device__ int    g_i64;

__device__ __forceinline__ float sigf(float x) { return 1.0f / (1.0f + expf(-x)); }
__device__ __forceinline__ float san(float x) {
    return (x == x && x > -1e30f && x < 1e30f) ? x : 0.0f;
}

// ---------------- detect index dtype (int32 vs int64) --------------------
__global__ void __launch_bounds__(256) detect_i64_k(const int* __restrict__ sent) {
    __shared__ int any;
    if (threadIdx.x == 0) any = 0;
    __syncthreads();
    int v = 0;
    for (int i = threadIdx.x; i < 1024; i += 256) v |= sent[2 * i + 1];
    if (v) atomicOr(&any, 1);
    __syncthreads();
    if (threadIdx.x == 0) g_i64 = (any == 0) ? 1 : 0;
}

// ---------------- 1) gather x = [emb[sentence], extra_emb[extra]] --------
__global__ void __launch_bounds__(256) gather_x_k(
    const void* __restrict__ sentv, const void* __restrict__ extrav,
    const float* __restrict__ emb, const float* __restrict__ xemb)
{
    int idx = blockIdx.x * 256 + threadIdx.x;
    if (idx >= SS * DXE) return;
    int t = idx / DXE;
    int d = idx - t * DXE;
    int wide = g_i64;
    float v;
    if (d < 256) {
        long s = wide ? (long)((const long long*)sentv)[t]
                      : (long)((const int*)sentv)[t];
        if (s < 0) s = 0; if (s > 99999) s = 99999;
        v = emb[s * 256 + d];
    } else {
        long s = wide ? (long)((const long long*)extrav)[t]
                      : (long)((const int*)extrav)[t];
        if (s < 0) s = 0; if (s > 999) s = 999;
        v = xemb[s * 64 + (d - 256)];
    }
    g_x[idx] = v;
}

// ---------------- 2) gx GEMM: [2048,320] x [320,2048] + bias -------------
__global__ void __launch_bounds__(256) gemm_gx_k(
    const float* __restrict__ wf, const float* __restrict__ wb,
    const float* __restrict__ bif, const float* __restrict__ bhf,
    const float* __restrict__ bib, const float* __restrict__ bhb)
{
    __shared__ __align__(16) float As[32 * 68];
    __shared__ __align__(16) float Bs[32 * 68];
    int n0 = blockIdx.x * 64;
    int t0 = blockIdx.y * 64;
    int back = (n0 >= 1024);
    const float* W = back ? wb : wf;
    int nb = back ? (n0 - 1024) : n0;
    int tid = threadIdx.x;
    int tm = tid >> 4, tn = tid & 15;
    float acc[4][4];
#pragma unroll
    for (int a = 0; a < 4; a++)
#pragma unroll
        for (int b2 = 0; b2 < 4; b2++) acc[a][b2] = 0.f;

    for (int k0 = 0; k0 < DXE; k0 += 32) {
        __syncthreads();
        for (int l = tid; l < 2048; l += 256) {
            int mm = l >> 5, kk = l & 31;
            As[kk * 68 + mm] = g_x[(t0 + mm) * DXE + k0 + kk];
            Bs[kk * 68 + mm] = W[(nb + mm) * DXE + k0 + kk];
        }
        __syncthreads();
#pragma unroll
        for (int kk = 0; kk < 32; kk++) {
            float4 av = *(const float4*)&As[kk * 68 + tm * 4];
            float4 bv = *(const float4*)&Bs[kk * 68 + tn * 4];
            float aa[4] = {av.x, av.y, av.z, av.w};
            float bb[4] = {bv.x, bv.y, bv.z, bv.w};
#pragma unroll
            for (int a = 0; a < 4; a++)
#pragma unroll
                for (int b2 = 0; b2 < 4; b2++)
                    acc[a][b2] = fmaf(aa[a], bb[b2], acc[a][b2]);
        }
    }
    float* gout = g_gx + (back ? SS * 1024 : 0);
#pragma unroll
    for (int b2 = 0; b2 < 4; b2++) {
        int nn = nb + tn * 4 + b2;
        float bias = back ? (bib[nn] + bhb[nn]) : (bif[nn] + bhf[nn]);
#pragma unroll
        for (int a = 0; a < 4; a++) {
            int tg = t0 + tm * 4 + a;
            gout[tg * 1024 + nn] = acc[a][b2] + bias;
        }
    }
}

// ---------------- 3) LSTM recurrence: cluster 8 CTAs/dir, mbarrier sync --
// Double-buffered h + per-CTA DSMEM mbarrier (count 256 = 8 CTAs x 32
// lanes) replaces barrier.cluster (~490cyc) with try_wait (~60-90cyc).
// Safety: reader of h_t finishes before any writer of h_{t+2} can pass
// wait(t+1), so one-step skew cannot corrupt the alternate buffer.
__global__ void __launch_bounds__(512, 1) __cluster_dims__(8, 1, 1)
lstm_clu_k(const float* __restrict__ whhf, const float* __restrict__ whhb)
{
    int bid = blockIdx.x;
    int dir = bid >> 3;
    int j = bid & 7;                       // cluster rank
    const float* whh = dir ? whhb : whhf;
    const float* gxd = g_gx + dir * (SS * 1024);
    float* hout = g_hall + dir * (SS * HH);

    int tid = threadIdx.x;
    int rg = tid >> 4, cc = tid & 15;      // rg 0..31, cc 0..15
    int gate = rg >> 3;                    // 0..3

    __shared__ __align__(16) float hs[2][16 * 17];   // double-buffered h
    __shared__ float gd[128];
    __shared__ __align__(8) unsigned long long mbar;

    float w[4][16];
#pragma unroll
    for (int q = 0; q < 4; q++) {
        int e = (rg & 7) * 4 + q;
        int grow = gate * 256 + j * 32 + e;
        const float* wp = whh + grow * HH + cc * 16;
#pragma unroll
        for (int k = 0; k < 16; k++) w[q][k] = wp[k];
    }
    for (int l = tid; l < 2 * 16 * 17; l += 512) ((float*)hs)[l] = 0.f;
    uint32_t mbar_a = (uint32_t)__cvta_generic_to_shared(&mbar);
    if (tid == 0) {
        asm volatile("mbarrier.init.shared.b64 [%0], %1;"
                     :: "r"(mbar_a), "r"(256) : "memory");
    }
    float creg = 0.f;

    float gxv[4] = {0.f, 0.f, 0.f, 0.f};
    if (tid < 32) {
        int idx0 = dir ? (SS - 1) : 0;
#pragma unroll
        for (int g = 0; g < 4; g++)
            gxv[g] = __ldcg(&gxd[idx0 * 1024 + g * 256 + j * 32 + tid]);
    }
    // my h element's padded smem offsets in both buffers
    uint32_t ha[2] = {0, 0};
    if (tid < 32) {
        int e = j * 32 + tid;
        int off = (e >> 4) * 17 + (e & 15);
        ha[0] = (uint32_t)__cvta_generic_to_shared(&hs[0][off]);
        ha[1] = (uint32_t)__cvta_generic_to_shared(&hs[1][off]);
    }
    // mbar init + zeroed buffers visible cluster-wide before any traffic
    asm volatile("barrier.cluster.arrive.aligned;" ::: "memory");
    asm volatile("barrier.cluster.wait.aligned;" ::: "memory");

    for (int t = 0; t < SS; t++) {
        int idx_t = dir ? (SS - 1 - t) : t;

        float gxn[4] = {0.f, 0.f, 0.f, 0.f};
        if (tid < 32 && t + 1 < SS) {
            int idxn = dir ? (SS - 2 - t) : (t + 1);
#pragma unroll
            for (int g = 0; g < 4; g++)
                gxn[g] = __ldcg(&gxd[idxn * 1024 + g * 256 + j * 32 + tid]);
        }

        // h_{t-1} lives in buffer (t+1)&1 (t=0 reads zeroed buf 1)
        const float* hb = hs[(t + 1) & 1];
        float hv[16];
#pragma unroll
        for (int k = 0; k < 16; k++) hv[k] = hb[cc * 17 + k];
        float a0 = 0.f, a1 = 0.f, a2 = 0.f, a3 = 0.f;
#pragma unroll
        for (int k = 0; k < 16; k++) {
            a0 = fmaf(w[0][k], hv[k], a0);
            a1 = fmaf(w[1][k], hv[k], a1);
            a2 = fmaf(w[2][k], hv[k], a2);
            a3 = fmaf(w[3][k], hv[k], a3);
        }
#pragma unroll
        for (int off = 8; off >= 1; off >>= 1) {
            a0 += __shfl_xor_sync(0xffffffffu, a0, off, 16);
            a1 += __shfl_xor_sync(0xffffffffu, a1, off, 16);
            a2 += __shfl_xor_sync(0xffffffffu, a2, off, 16);
            a3 += __shfl_xor_sync(0xffffffffu, a3, off, 16);
        }
        if (cc == 0) {
            int base = gate * 32 + (rg & 7) * 4;
            gd[base + 0] = a0;
            gd[base + 1] = a1;
            gd[base + 2] = a2;
            gd[base + 3] = a3;
        }
        __syncthreads();

        if (tid < 32) {
            float ai = san(gd[tid]      + gxv[0]);
            float af = san(gd[32 + tid] + gxv[1]);
            float ag = san(gd[64 + tid] + gxv[2]);
            float ao = san(gd[96 + tid] + gxv[3]);
            float ig = sigf(ai), fg = sigf(af);
            float gg = tanhf(ag), og = sigf(ao);
            creg = fg * creg + ig * gg;
            float hval = og * tanhf(creg);
            uint32_t dsta = ha[t & 1];
            // push my h into every CTA's buffer (self included)
#pragma unroll
            for (int r = 0; r < 8; r++) {
                uint32_t ra;
                asm volatile("mapa.shared::cluster.u32 %0, %1, %2;"
                             : "=r"(ra) : "r"(dsta), "r"(r));
                asm volatile("st.shared::cluster.f32 [%0], %1;"
                             :: "r"(ra), "f"(hval) : "memory");
            }
            // release my stores at cluster scope, then arrive everywhere
            asm volatile("fence.acq_rel.cluster;" ::: "memory");
#pragma unroll
            for (int r = 0; r < 8; r++) {
                asm volatile(
                    "{\n\t.reg .b32 ra;\n\t"
                    "mapa.shared::cluster.u32 ra, %0, %1;\n\t"
                    "mbarrier.arrive.shared::cluster.b64 _, [ra];\n\t}"
                    :: "r"(mbar_a), "r"(r) : "memory");
            }
            hout[idx_t * HH + j * 32 + tid] = hval;
            gxv[0] = gxn[0]; gxv[1] = gxn[1]; gxv[2] = gxn[2]; gxv[3] = gxn[3];
        }
        // wait for all 256 arrivals of this step (phase parity = t&1)
        {
            uint32_t par = (uint32_t)(t & 1);
            uint32_t done;
            asm volatile(
                "{\n\t.reg .pred p;\n\t"
                "mbarrier.try_wait.parity.acquire.cta.shared::cta.b64 p, [%1], %2;\n\t"
                "selp.b32 %0, 1, 0, p;\n\t}"
                : "=r"(done) : "r"(mbar_a), "r"(par) : "memory");
            if (!done) {
                asm volatile(
                    "{\n\t.reg .pred P1;\n\t"
                    "WL_%=:\n\t"
                    "mbarrier.try_wait.parity.acquire.cta.shared::cta.b64 P1, [%0], %1, 0x989680;\n\t"
                    "@P1 bra.uni WD_%=;\n\t"
                    "bra.uni WL_%=;\n\t"
                    "WD_%=:\n\t}"
                    :: "r"(mbar_a), "r"(par) : "memory");
            }
            asm volatile("fence.acq_rel.cluster;" ::: "memory");
        }
    }
}

// ---------------- 4) feats = lstm_out @ fc_w^T + fc_b --------------------
__global__ void __launch_bounds__(256) feats_k(
    const float* __restrict__ fcw, const float* __restrict__ fcb)
{
    __shared__ float hsm[4][512];
    __shared__ float wsm[64 * 65];
    int t0 = blockIdx.x * 4;
    int tid = threadIdx.x;
    for (int l = tid; l < 2048; l += 256) {
        int tl = l >> 9, k = l & 511;
        int t = t0 + tl;
        hsm[tl][k] = (k < 256) ? g_hall[t * 256 + k]
                               : g_hall[SS * 256 + t * 256 + (k - 256)];
    }
    float acc = 0.f;
    int tl = tid >> 6, tau = tid & 63;
    for (int kt = 0; kt < 8; kt++) {
        __syncthreads();
        for (int l = tid; l < 4096; l += 256) {
            int r = l >> 6, c = l & 63;
            wsm[r * 65 + c] = fcw[r * 512 + kt * 64 + c];
        }
        __syncthreads();
#pragma unroll
        for (int c = 0; c < 64; c++)
            acc = fmaf(hsm[tl][kt * 64 + c], wsm[tau * 65 + c], acc);
    }
    g_feats[(t0 + tl) * 64 + tau] = acc + fcb[tau];
}

// ---------------- 5) Viterbi; bp in DYNAMIC smem; FLOAT32 output ---------
#define VIT_SMEM (((64 * 65 + 128 + 64) * 4) + (SS - 1) * 64)
__global__ void __launch_bounds__(256) viterbi_k(
    const float* __restrict__ cstart, const float* __restrict__ cend,
    const float* __restrict__ ctrans, float* __restrict__ out)
{
    extern __shared__ char vsm[];
    float* tt = (float*)vsm;                       // 64*65
    float* sc = tt + 64 * 65;                      // 128
    float* fin = sc + 128;                         // 64
    unsigned char* bp = (unsigned char*)(fin + 64);

    const int L = SS;
    int tid = threadIdx.x;

    for (int l = tid; l < 4096; l += 256) {
        int i = l >> 6, jj = l & 63;
        tt[jj * 65 + i] = ctrans[i * 64 + jj];
    }
    if (tid < 64) sc[tid] = cstart[tid] + san(g_feats[tid]);
    __syncthreads();

    int j = tid >> 2, s = tid & 3;
    float fcur = 0.f;
    if (s == 0) fcur = san(g_feats[1 * 64 + j]);

    for (int t = 1; t < L; t++) {
        float fnext = 0.f;
        if (s == 0 && t + 1 < L) fnext = san(g_feats[(t + 1) * 64 + j]);
        const float* cur = sc + (((t - 1) & 1) << 6);
        float* nxt = sc + ((t & 1) << 6);

        float best = -3.0e38f; int bi = 0;
#pragma unroll
        for (int i2 = 0; i2 < 16; i2++) {
            int i = s * 16 + i2;
            float v = cur[i] + tt[j * 65 + i];
            if (v > best) { best = v; bi = i; }
        }
#pragma unroll
        for (int off = 1; off <= 2; off <<= 1) {
            float ov = __shfl_xor_sync(0xffffffffu, best, off, 4);
            int   oi = __shfl_xor_sync(0xffffffffu, bi, off, 4);
            if (ov > best || (ov == best && oi < bi)) { best = ov; bi = oi; }
        }
        if (s == 0) {
            nxt[j] = best + fcur;
            bp[(t - 1) * 64 + j] = (unsigned char)bi;
        }
        fcur = fnext;
        __syncthreads();
    }

    if (tid < 64) fin[tid] = sc[(((L - 1) & 1)) * 64 + tid] + cend[tid];
    __syncthreads();
    if (tid == 0) {
        float bv = fin[0]; int bt = 0;
        for (int i = 1; i < 64; i++)
            if (fin[i] > bv) { bv = fin[i]; bt = i; }
        out[L - 1] = (float)bt;
        int tag = bt;
        for (int k = L - 2; k >= 0; k--) {
            tag = bp[k * 64 + tag];
            out[k] = (float)tag;
        }
    }
}

// ---------------- size-based input resolver ------------------------------
struct InPtrs {
    const void *sent, *extra;
    const float *emb, *xemb;
    const float *wihf, *whhf, *bf0, *bf1;
    const float *wihb, *whhb, *bb0, *bb1;
    const float *fcw, *fcb, *cstart, *cend, *ctrans;
};

static bool resolve_inputs(void* const* d_in, const int* in_sizes, int n_in,
                           InPtrs& P)
{
    long mult = 1;
    for (int i = 0; i < n_in; i++)
        if (in_sizes[i] == 102400000) { mult = 4; break; }

    int idxL[4], nIdx = 0, wihL[4], nWih = 0, whhL[4], nWhh = 0;
    int bL[8], nB = 0, smL[6], nSm = 0;
    int iEmb = -1, iXemb = -1, iFcw = -1, iTr = -1;

    for (int i = 0; i < n_in; i++) {
        long s = (long)in_sizes[i] / mult;
        if      (s == 25600000) iEmb = i;
        else if (s == 64000)    iXemb = i;
        else if (s == 32768)    iFcw = i;
        else if (s == 4096)     iTr = i;
        else if (s == 327680 && nWih < 4) wihL[nWih++] = i;
        else if (s == 262144 && nWhh < 4) whhL[nWhh++] = i;
        else if (s == 1024   && nB < 8)   bL[nB++] = i;
        else if (s == 2048   && nIdx < 4) idxL[nIdx++] = i;
        else if (s == 64     && nSm < 6)  smL[nSm++] = i;
    }
    if (iEmb < 0 || iXemb < 0 || iFcw < 0 || iTr < 0 ||
        nWih < 2 || nWhh < 2 || nB < 4 || nIdx < 2 || nSm < 3)
        return false;

    bool alpha = ((long)in_sizes[0] / mult != 2048);
    if (!alpha) {
        P.sent = d_in[idxL[0]];  P.extra = d_in[idxL[1]];
        P.wihf = (const float*)d_in[wihL[0]]; P.wihb = (const float*)d_in[wihL[1]];
        P.whhf = (const float*)d_in[whhL[0]]; P.whhb = (const float*)d_in[whhL[1]];
        P.bf0 = (const float*)d_in[bL[0]]; P.bf1 = (const float*)d_in[bL[1]];
        P.bb0 = (const float*)d_in[bL[2]]; P.bb1 = (const float*)d_in[bL[3]];
        P.fcb = (const float*)d_in[smL[0]];
        P.cstart = (const float*)d_in[smL[1]]; P.cend = (const float*)d_in[smL[2]];
    } else {
        P.sent = d_in[idxL[1]];  P.extra = d_in[idxL[0]];
        P.wihf = (const float*)d_in[wihL[1]]; P.wihb = (const float*)d_in[wihL[0]];
        P.whhf = (const float*)d_in[whhL[1]]; P.whhb = (const float*)d_in[whhL[0]];
        P.bf0 = (const float*)d_in[bL[1]]; P.bf1 = (const float*)d_in[bL[3]];
        P.bb0 = (const float*)d_in[bL[0]]; P.bb1 = (const float*)d_in[bL[2]];
        P.cend = (const float*)d_in[smL[0]];
        P.cstart = (const float*)d_in[smL[1]]; P.fcb = (const float*)d_in[smL[2]];
    }
    P.emb  = (const float*)d_in[iEmb];
    P.xemb = (const float*)d_in[iXemb];
    P.fcw  = (const float*)d_in[iFcw];
    P.ctrans = (const float*)d_in[iTr];
    return true;
}

// ---------------- launch -------------------------------------------------
extern "C" void kernel_launch(void* const* d_in, const int* in_sizes, int n_in,
                              void* d_out, int out_size)
{
    InPtrs P;
    if (!resolve_inputs(d_in, in_sizes, n_in, P)) {
        P.sent = d_in[0];  P.extra = d_in[1];
        P.emb = (const float*)d_in[4]; P.xemb = (const float*)d_in[5];
        P.wihf = (const float*)d_in[6]; P.whhf = (const float*)d_in[7];
        P.bf0 = (const float*)d_in[8]; P.bf1 = (const float*)d_in[9];
        P.wihb = (const float*)d_in[10]; P.whhb = (const float*)d_in[11];
        P.bb0 = (const float*)d_in[12]; P.bb1 = (const float*)d_in[13];
        P.fcw = (const float*)d_in[14]; P.fcb = (const float*)d_in[15];
        P.cstart = (const float*)d_in[16]; P.cend = (const float*)d_in[17];
        P.ctrans = (const float*)d_in[18];
    }
    float* out = (float*)d_out;

    detect_i64_k<<<1, 256>>>((const int*)P.sent);
    gather_x_k<<<(SS * DXE + 255) / 256, 256>>>(P.sent, P.extra, P.emb, P.xemb);
    gemm_gx_k<<<dim3(32, 32), 256>>>(P.wihf, P.wihb, P.bf0, P.bf1, P.bb0, P.bb1);
    lstm_clu_k<<<16, 512>>>(P.whhf, P.whhb);
    feats_k<<<SS / 4, 256>>>(P.fcw, P.fcb);
    static bool vit_attr_done = false;
    if (!vit_attr_done) {
        cudaFuncSetAttribute(viterbi_k,
                             cudaFuncAttributeMaxDynamicSharedMemorySize,
                             VIT_SMEM);
        vit_attr_done = true;
    }
    viterbi_k<<<1, 256, VIT_SMEM>>>(P.cstart, P.cend, P.ctrans, out);
}

// round 16
// speedup vs baseline: 1.2074x; 1.2074x over previous
#include <cuda_runtime.h>
#include <cstdint>

#define SS   2048
#define HH   256
#define DXE  320
#define NT   64

// ---------------- device scratch (no allocations allowed) ----------------
__device__ float  g_x[SS * DXE];
__device__ float  g_gx[2 * SS * 1024];
__device__ float  g_hall[2 * SS * HH];
__device__ float  g_feats[SS * NT];
__device__ int    g_i64;

__device__ __forceinline__ float sigf(float x) { return 1.0f / (1.0f + expf(-x)); }
__device__ __forceinline__ float san(float x) {
    return (x == x && x > -1e30f && x < 1e30f) ? x : 0.0f;
}
__device__ __forceinline__ void fma2(unsigned long long& acc,
                                     unsigned long long a,
                                     unsigned long long b) {
    asm("fma.rn.f32x2 %0, %1, %2, %0;" : "+l"(acc) : "l"(a), "l"(b));
}

// ---------------- detect index dtype (int32 vs int64) --------------------
__global__ void __launch_bounds__(256) detect_i64_k(const int* __restrict__ sent) {
    __shared__ int any;
    if (threadIdx.x == 0) any = 0;
    __syncthreads();
    int v = 0;
    for (int i = threadIdx.x; i < 1024; i += 256) v |= sent[2 * i + 1];
    if (v) atomicOr(&any, 1);
    __syncthreads();
    if (threadIdx.x == 0) g_i64 = (any == 0) ? 1 : 0;
}

// ---------------- 1) gather x = [emb[sentence], extra_emb[extra]] --------
__global__ void __launch_bounds__(256) gather_x_k(
    const void* __restrict__ sentv, const void* __restrict__ extrav,
    const float* __restrict__ emb, const float* __restrict__ xemb)
{
    int idx = blockIdx.x * 256 + threadIdx.x;
    if (idx >= SS * DXE) return;
    int t = idx / DXE;
    int d = idx - t * DXE;
    int wide = g_i64;
    float v;
    if (d < 256) {
        long s = wide ? (long)((const long long*)sentv)[t]
                      : (long)((const int*)sentv)[t];
        if (s < 0) s = 0; if (s > 99999) s = 99999;
        v = emb[s * 256 + d];
    } else {
        long s = wide ? (long)((const long long*)extrav)[t]
                      : (long)((const int*)extrav)[t];
        if (s < 0) s = 0; if (s > 999) s = 999;
        v = xemb[s * 64 + (d - 256)];
    }
    g_x[idx] = v;
}

// ---------------- 2) gx GEMM: [2048,320] x [320,2048] + bias -------------
__global__ void __launch_bounds__(256) gemm_gx_k(
    const float* __restrict__ wf, const float* __restrict__ wb,
    const float* __restrict__ bif, const float* __restrict__ bhf,
    const float* __restrict__ bib, const float* __restrict__ bhb)
{
    __shared__ __align__(16) float As[32 * 68];
    __shared__ __align__(16) float Bs[32 * 68];
    int n0 = blockIdx.x * 64;
    int t0 = blockIdx.y * 64;
    int back = (n0 >= 1024);
    const float* W = back ? wb : wf;
    int nb = back ? (n0 - 1024) : n0;
    int tid = threadIdx.x;
    int tm = tid >> 4, tn = tid & 15;
    float acc[4][4];
#pragma unroll
    for (int a = 0; a < 4; a++)
#pragma unroll
        for (int b2 = 0; b2 < 4; b2++) acc[a][b2] = 0.f;

    for (int k0 = 0; k0 < DXE; k0 += 32) {
        __syncthreads();
        for (int l = tid; l < 2048; l += 256) {
            int mm = l >> 5, kk = l & 31;
            As[kk * 68 + mm] = g_x[(t0 + mm) * DXE + k0 + kk];
            Bs[kk * 68 + mm] = W[(nb + mm) * DXE + k0 + kk];
        }
        __syncthreads();
#pragma unroll
        for (int kk = 0; kk < 32; kk++) {
            float4 av = *(const float4*)&As[kk * 68 + tm * 4];
            float4 bv = *(const float4*)&Bs[kk * 68 + tn * 4];
            float aa[4] = {av.x, av.y, av.z, av.w};
            float bb[4] = {bv.x, bv.y, bv.z, bv.w};
#pragma unroll
            for (int a = 0; a < 4; a++)
#pragma unroll
                for (int b2 = 0; b2 < 4; b2++)
                    acc[a][b2] = fmaf(aa[a], bb[b2], acc[a][b2]);
        }
    }
    float* gout = g_gx + (back ? SS * 1024 : 0);
#pragma unroll
    for (int b2 = 0; b2 < 4; b2++) {
        int nn = nb + tn * 4 + b2;
        float bias = back ? (bib[nn] + bhb[nn]) : (bif[nn] + bhf[nn]);
#pragma unroll
        for (int a = 0; a < 4; a++) {
            int tg = t0 + tm * 4 + a;
            gout[tg * 1024 + nn] = acc[a][b2] + bias;
        }
    }
}

// ---------------- 3) LSTM: cluster 8 CTAs/dir, barrier.cluster sync, -----
// double-buffered h (race-free), f32x2 packed matvec (FFMA2 halves issue).
// Layout: h element e at buf[b][(e>>4)*18 + (e&15)] (18-pad: 8B-aligned
// float2 reads, conflict-free: 9cc mod 32 distinct for cc=0..15).
__global__ void __launch_bounds__(512, 1) __cluster_dims__(8, 1, 1)
lstm_clu_k(const float* __restrict__ whhf, const float* __restrict__ whhb)
{
    int bid = blockIdx.x;
    int dir = bid >> 3;
    int j = bid & 7;                       // cluster rank
    const float* whh = dir ? whhb : whhf;
    const float* gxd = g_gx + dir * (SS * 1024);
    float* hout = g_hall + dir * (SS * HH);

    int tid = threadIdx.x;
    int rg = tid >> 4, cc = tid & 15;      // rg 0..31, cc 0..15
    int gate = rg >> 3;                    // 0..3

    __shared__ __align__(16) float hs[2][16 * 18];   // double-buffered h
    __shared__ float gd[128];

    // weights as packed f32x2 pairs: w2[q][k2] = {W[row][cc*16+2k2], ...+1}
    unsigned long long w2[4][8];
#pragma unroll
    for (int q = 0; q < 4; q++) {
        int e = (rg & 7) * 4 + q;
        int grow = gate * 256 + j * 32 + e;
        const float* wp = whh + grow * HH + cc * 16;
#pragma unroll
        for (int k2 = 0; k2 < 8; k2++) {
            float2 tw = { wp[2 * k2], wp[2 * k2 + 1] };
            w2[q][k2] = *(unsigned long long*)&tw;
        }
    }
    for (int l = tid; l < 2 * 16 * 18; l += 512) ((float*)hs)[l] = 0.f;
    float creg = 0.f;

    float gxv[4] = {0.f, 0.f, 0.f, 0.f};
    if (tid < 32) {
        int idx0 = dir ? (SS - 1) : 0;
#pragma unroll
        for (int g = 0; g < 4; g++)
            gxv[g] = __ldcg(&gxd[idx0 * 1024 + g * 256 + j * 32 + tid]);
    }
    // my h element's smem addresses in both buffers
    uint32_t ha[2] = {0, 0};
    if (tid < 32) {
        int e = j * 32 + tid;
        int off = (e >> 4) * 18 + (e & 15);
        ha[0] = (uint32_t)__cvta_generic_to_shared(&hs[0][off]);
        ha[1] = (uint32_t)__cvta_generic_to_shared(&hs[1][off]);
    }
    // zeroed buffers visible cluster-wide before any remote traffic
    asm volatile("barrier.cluster.arrive.aligned;" ::: "memory");
    asm volatile("barrier.cluster.wait.aligned;" ::: "memory");

    for (int t = 0; t < SS; t++) {
        int idx_t = dir ? (SS - 1 - t) : t;

        float gxn[4] = {0.f, 0.f, 0.f, 0.f};
        if (tid < 32 && t + 1 < SS) {
            int idxn = dir ? (SS - 2 - t) : (t + 1);
#pragma unroll
            for (int g = 0; g < 4; g++)
                gxn[g] = __ldcg(&gxd[idxn * 1024 + g * 256 + j * 32 + tid]);
        }

        // h_{t-1} in buffer (t+1)&1 (t=0 reads zeroed buf 1)
        const unsigned long long* hrow =
            (const unsigned long long*)hs[(t + 1) & 1] + cc * 9;
        unsigned long long ac0 = 0ull, ac1 = 0ull, ac2 = 0ull, ac3 = 0ull;
#pragma unroll
        for (int k2 = 0; k2 < 8; k2++) {
            unsigned long long h2 = hrow[k2];
            fma2(ac0, w2[0][k2], h2);
            fma2(ac1, w2[1][k2], h2);
            fma2(ac2, w2[2][k2], h2);
            fma2(ac3, w2[3][k2], h2);
        }
        float2 f0 = *(float2*)&ac0, f1 = *(float2*)&ac1;
        float2 f2 = *(float2*)&ac2, f3 = *(float2*)&ac3;
        float a0 = f0.x + f0.y, a1 = f1.x + f1.y;
        float a2 = f2.x + f2.y, a3 = f3.x + f3.y;
#pragma unroll
        for (int off = 8; off >= 1; off >>= 1) {
            a0 += __shfl_xor_sync(0xffffffffu, a0, off, 16);
            a1 += __shfl_xor_sync(0xffffffffu, a1, off, 16);
            a2 += __shfl_xor_sync(0xffffffffu, a2, off, 16);
            a3 += __shfl_xor_sync(0xffffffffu, a3, off, 16);
        }
        if (cc == 0) {
            int base = gate * 32 + (rg & 7) * 4;
            gd[base + 0] = a0;
            gd[base + 1] = a1;
            gd[base + 2] = a2;
            gd[base + 3] = a3;
        }
        __syncthreads();

        if (tid < 32) {
            float ai = san(gd[tid]      + gxv[0]);
            float af = san(gd[32 + tid] + gxv[1]);
            float ag = san(gd[64 + tid] + gxv[2]);
            float ao = san(gd[96 + tid] + gxv[3]);
            float ig = sigf(ai), fg = sigf(af);
            float gg = tanhf(ag), og = sigf(ao);
            creg = fg * creg + ig * gg;
            float hval = og * tanhf(creg);
            uint32_t dsta = ha[t & 1];     // write h_t into buffer t&1
#pragma unroll
            for (int r = 0; r < 8; r++) {
                uint32_t ra;
                asm volatile("mapa.shared::cluster.u32 %0, %1, %2;"
                             : "=r"(ra) : "r"(dsta), "r"(r));
                asm volatile("st.shared::cluster.f32 [%0], %1;"
                             :: "r"(ra), "f"(hval) : "memory");
            }
            hout[idx_t * HH + j * 32 + tid] = hval;
            gxv[0] = gxn[0]; gxv[1] = gxn[1]; gxv[2] = gxn[2]; gxv[3] = gxn[3];
        }
        // arrive = release (orders cluster smem stores), wait = acquire
        asm volatile("barrier.cluster.arrive.aligned;" ::: "memory");
        asm volatile("barrier.cluster.wait.aligned;" ::: "memory");
    }
}

// ---------------- 4) feats = lstm_out @ fc_w^T + fc_b --------------------
__global__ void __launch_bounds__(256) feats_k(
    const float* __restrict__ fcw, const float* __restrict__ fcb)
{
    __shared__ float hsm[4][512];
    __shared__ float wsm[64 * 65];
    int t0 = blockIdx.x * 4;
    int tid = threadIdx.x;
    for (int l = tid; l < 2048; l += 256) {
        int tl = l >> 9, k = l & 511;
        int t = t0 + tl;
        hsm[tl][k] = (k < 256) ? g_hall[t * 256 + k]
                               : g_hall[SS * 256 + t * 256 + (k - 256)];
    }
    float acc = 0.f;
    int tl = tid >> 6, tau = tid & 63;
    for (int kt = 0; kt < 8; kt++) {
        __syncthreads();
        for (int l = tid; l < 4096; l += 256) {
            int r = l >> 6, c = l & 63;
            wsm[r * 65 + c] = fcw[r * 512 + kt * 64 + c];
        }
        __syncthreads();
#pragma unroll
        for (int c = 0; c < 64; c++)
            acc = fmaf(hsm[tl][kt * 64 + c], wsm[tau * 65 + c], acc);
    }
    g_feats[(t0 + tl) * 64 + tau] = acc + fcb[tau];
}

// ---------------- 5) Viterbi; bp in DYNAMIC smem; FLOAT32 output ---------
#define VIT_SMEM (((64 * 65 + 128 + 64) * 4) + (SS - 1) * 64)
__global__ void __launch_bounds__(256) viterbi_k(
    const float* __restrict__ cstart, const float* __restrict__ cend,
    const float* __restrict__ ctrans, float* __restrict__ out)
{
    extern __shared__ char vsm[];
    float* tt = (float*)vsm;
    float* sc = tt + 64 * 65;
    float* fin = sc + 128;
    unsigned char* bp = (unsigned char*)(fin + 64);

    const int L = SS;
    int tid = threadIdx.x;

    for (int l = tid; l < 4096; l += 256) {
        int i = l >> 6, jj = l & 63;
        tt[jj * 65 + i] = ctrans[i * 64 + jj];
    }
    if (tid < 64) sc[tid] = cstart[tid] + san(g_feats[tid]);
    __syncthreads();

    int j = tid >> 2, s = tid & 3;
    float fcur = 0.f;
    if (s == 0) fcur = san(g_feats[1 * 64 + j]);

    for (int t = 1; t < L; t++) {
        float fnext = 0.f;
        if (s == 0 && t + 1 < L) fnext = san(g_feats[(t + 1) * 64 + j]);
        const float* cur = sc + (((t - 1) & 1) << 6);
        float* nxt = sc + ((t & 1) << 6);

        float best = -3.0e38f; int bi = 0;
#pragma unroll
        for (int i2 = 0; i2 < 16; i2++) {
            int i = s * 16 + i2;
            float v = cur[i] + tt[j * 65 + i];
            if (v > best) { best = v; bi = i; }
        }
#pragma unroll
        for (int off = 1; off <= 2; off <<= 1) {
            float ov = __shfl_xor_sync(0xffffffffu, best, off, 4);
            int   oi = __shfl_xor_sync(0xffffffffu, bi, off, 4);
            if (ov > best || (ov == best && oi < bi)) { best = ov; bi = oi; }
        }
        if (s == 0) {
            nxt[j] = best + fcur;
            bp[(t - 1) * 64 + j] = (unsigned char)bi;
        }
        fcur = fnext;
        __syncthreads();
    }

    if (tid < 64) fin[tid] = sc[(((L - 1) & 1)) * 64 + tid] + cend[tid];
    __syncthreads();
    if (tid == 0) {
        float bv = fin[0]; int bt = 0;
        for (int i = 1; i < 64; i++)
            if (fin[i] > bv) { bv = fin[i]; bt = i; }
        out[L - 1] = (float)bt;
        int tag = bt;
        for (int k = L - 2; k >= 0; k--) {
            tag = bp[k * 64 + tag];
            out[k] = (float)tag;
        }
    }
}

// ---------------- size-based input resolver ------------------------------
struct InPtrs {
    const void *sent, *extra;
    const float *emb, *xemb;
    const float *wihf, *whhf, *bf0, *bf1;
    const float *wihb, *whhb, *bb0, *bb1;
    const float *fcw, *fcb, *cstart, *cend, *ctrans;
};

static bool resolve_inputs(void* const* d_in, const int* in_sizes, int n_in,
                           InPtrs& P)
{
    long mult = 1;
    for (int i = 0; i < n_in; i++)
        if (in_sizes[i] == 102400000) { mult = 4; break; }

    int idxL[4], nIdx = 0, wihL[4], nWih = 0, whhL[4], nWhh = 0;
    int bL[8], nB = 0, smL[6], nSm = 0;
    int iEmb = -1, iXemb = -1, iFcw = -1, iTr = -1;

    for (int i = 0; i < n_in; i++) {
        long s = (long)in_sizes[i] / mult;
        if      (s == 25600000) iEmb = i;
        else if (s == 64000)    iXemb = i;
        else if (s == 32768)    iFcw = i;
        else if (s == 4096)     iTr = i;
        else if (s == 327680 && nWih < 4) wihL[nWih++] = i;
        else if (s == 262144 && nWhh < 4) whhL[nWhh++] = i;
        else if (s == 1024   && nB < 8)   bL[nB++] = i;
        else if (s == 2048   && nIdx < 4) idxL[nIdx++] = i;
        else if (s == 64     && nSm < 6)  smL[nSm++] = i;
    }
    if (iEmb < 0 || iXemb < 0 || iFcw < 0 || iTr < 0 ||
        nWih < 2 || nWhh < 2 || nB < 4 || nIdx < 2 || nSm < 3)
        return false;

    bool alpha = ((long)in_sizes[0] / mult != 2048);
    if (!alpha) {
        P.sent = d_in[idxL[0]];  P.extra = d_in[idxL[1]];
        P.wihf = (const float*)d_in[wihL[0]]; P.wihb = (const float*)d_in[wihL[1]];
        P.whhf = (const float*)d_in[whhL[0]]; P.whhb = (const float*)d_in[whhL[1]];
        P.bf0 = (const float*)d_in[bL[0]]; P.bf1 = (const float*)d_in[bL[1]];
        P.bb0 = (const float*)d_in[bL[2]]; P.bb1 = (const float*)d_in[bL[3]];
        P.fcb = (const float*)d_in[smL[0]];
        P.cstart = (const float*)d_in[smL[1]]; P.cend = (const float*)d_in[smL[2]];
    } else {
        P.sent = d_in[idxL[1]];  P.extra = d_in[idxL[0]];
        P.wihf = (const float*)d_in[wihL[1]]; P.wihb = (const float*)d_in[wihL[0]];
        P.whhf = (const float*)d_in[whhL[1]]; P.whhb = (const float*)d_in[whhL[0]];
        P.bf0 = (const float*)d_in[bL[1]]; P.bf1 = (const float*)d_in[bL[3]];
        P.bb0 = (const float*)d_in[bL[0]]; P.bb1 = (const float*)d_in[bL[2]];
        P.cend = (const float*)d_in[smL[0]];
        P.cstart = (const float*)d_in[smL[1]]; P.fcb = (const float*)d_in[smL[2]];
    }
    P.emb  = (const float*)d_in[iEmb];
    P.xemb = (const float*)d_in[iXemb];
    P.fcw  = (const float*)d_in[iFcw];
    P.ctrans = (const float*)d_in[iTr];
    return true;
}

// ---------------- launch -------------------------------------------------
extern "C" void kernel_launch(void* const* d_in, const int* in_sizes, int n_in,
                              void* d_out, int out_size)
{
    InPtrs P;
    if (!resolve_inputs(d_in, in_sizes, n_in, P)) {
        P.sent = d_in[0];  P.extra = d_in[1];
        P.emb = (const float*)d_in[4]; P.xemb = (const float*)d_in[5];
        P.wihf = (const float*)d_in[6]; P.whhf = (const float*)d_in[7];
        P.bf0 = (const float*)d_in[8]; P.bf1 = (const float*)d_in[9];
        P.wihb = (const float*)d_in[10]; P.whhb = (const float*)d_in[11];
        P.bb0 = (const float*)d_in[12]; P.bb1 = (const float*)d_in[13];
        P.fcw = (const float*)d_in[14]; P.fcb = (const float*)d_in[15];
        P.cstart = (const float*)d_in[16]; P.cend = (const float*)d_in[17];
        P.ctrans = (const float*)d_in[18];
    }
    float* out = (float*)d_out;

    detect_i64_k<<<1, 256>>>((const int*)P.sent);
    gather_x_k<<<(SS * DXE + 255) / 256, 256>>>(P.sent, P.extra, P.emb, P.xemb);
    gemm_gx_k<<<dim3(32, 32), 256>>>(P.wihf, P.wihb, P.bf0, P.bf1, P.bb0, P.bb1);
    lstm_clu_k<<<16, 512>>>(P.whhf, P.whhb);
    feats_k<<<SS / 4, 256>>>(P.fcw, P.fcb);
    static bool vit_attr_done = false;
    if (!vit_attr_done) {
        cudaFuncSetAttribute(viterbi_k,
                             cudaFuncAttributeMaxDynamicSharedMemorySize,
                             VIT_SMEM);
        vit_attr_done = true;
    }
    viterbi_k<<<1, 256, VIT_SMEM>>>(P.cstart, P.cend, P.ctrans, out);
}